// round 1
// baseline (speedup 1.0000x reference)
#include <cuda_runtime.h>
#include <math.h>

#define Bb 64
#define Tt 128
#define Ii 1024
#define Hh 4096
#define NNZ_IH 262144
#define NNZ_HH 1048576

// ---------------- device scratch (static, no allocations) ----------------
__device__ float g_xT[Tt * Ii * Bb];     // (T, I, B)
__device__ float g_h[Hh * Bb];           // current hidden (H, B)
__device__ float g_hact[Hh * Bb];        // tanh(pre) per step (H, B)

// hh CSR (rows 0..H-1), cols approx ascending within row
__device__ int   g_hh_ptr[Hh + 1];
__device__ int   g_hh_cnt[Hh];
__device__ int   g_hh_col[NNZ_HH];
__device__ float g_hh_val[NNZ_HH];

// temp (col-sorted) buffers, shared between hh and ih prep
__device__ int   g_cptr[Hh + 1];
__device__ int   g_ccnt[Hh];
__device__ int   g_trow[NNZ_HH];
__device__ int   g_tcol[NNZ_HH];
__device__ float g_tval[NNZ_HH];

// ih CSR
__device__ int   g_ih_ptr[Hh + 1];
__device__ int   g_ih_cnt[Hh];
__device__ int   g_ih_col[NNZ_IH];
__device__ float g_ih_val[NNZ_IH];

// ---------------- prep kernels ----------------

__global__ void k_zero_all() {
    int i = blockIdx.x * blockDim.x + threadIdx.x;   // 262144 threads
    if (i < Hh) { g_ccnt[i] = 0; g_hh_cnt[i] = 0; g_ih_cnt[i] = 0; }
    if (i < Hh * Bb) g_h[i] = 0.f;
}

__global__ void k_zero_ccnt() {
    int i = blockIdx.x * blockDim.x + threadIdx.x;
    if (i < Hh) g_ccnt[i] = 0;
}

// histogram of cols into g_ccnt and rows into (which==0 ? g_hh_cnt : g_ih_cnt)
__global__ void k_hist(const int* __restrict__ rows, const int* __restrict__ cols,
                       int n, int which) {
    int* rcnt = (which == 0) ? g_hh_cnt : g_ih_cnt;
    for (int i = blockIdx.x * blockDim.x + threadIdx.x; i < n;
         i += gridDim.x * blockDim.x) {
        atomicAdd(&g_ccnt[cols[i]], 1);
        atomicAdd(&rcnt[rows[i]], 1);
    }
}

// exclusive scan of a <=4096-entry count array; writes ptr[0..n] and resets
// the count array to cursor start positions. which: 0=g_ccnt/g_cptr,
// 1=g_hh_cnt/g_hh_ptr, 2=g_ih_cnt/g_ih_ptr. single block of 1024 threads.
__global__ void k_scan(int which, int n) {
    int* cnt = (which == 0) ? g_ccnt : (which == 1) ? g_hh_cnt : g_ih_cnt;
    int* ptr = (which == 0) ? g_cptr : (which == 1) ? g_hh_ptr : g_ih_ptr;
    __shared__ int s[4096];
    __shared__ int part[1024];
    int tid = threadIdx.x;
    for (int i = tid; i < 4096; i += 1024) s[i] = (i < n) ? cnt[i] : 0;
    __syncthreads();
    int b4 = tid * 4;
    int a0 = s[b4], a1 = s[b4 + 1], a2 = s[b4 + 2], a3 = s[b4 + 3];
    int sum = a0 + a1 + a2 + a3;
    part[tid] = sum;
    __syncthreads();
    for (int off = 1; off < 1024; off <<= 1) {
        int v = (tid >= off) ? part[tid - off] : 0;
        __syncthreads();
        part[tid] += v;
        __syncthreads();
    }
    int excl = part[tid] - sum;
    if (b4 < n) {
        int p0 = excl, p1 = excl + a0, p2 = excl + a0 + a1, p3 = excl + a0 + a1 + a2;
        ptr[b4] = p0;     cnt[b4] = p0;
        ptr[b4 + 1] = p1; cnt[b4 + 1] = p1;
        ptr[b4 + 2] = p2; cnt[b4 + 2] = p2;
        ptr[b4 + 3] = p3; cnt[b4 + 3] = p3;
    }
    if (tid == 1023) ptr[n] = part[1023];
}

// pass 1: bucket by col into tmp arrays (uses g_ccnt cursors)
__global__ void k_scatter_col(const int* __restrict__ rows, const int* __restrict__ cols,
                              const float* __restrict__ vals, int n) {
    for (int i = blockIdx.x * blockDim.x + threadIdx.x; i < n;
         i += gridDim.x * blockDim.x) {
        int c = cols[i];
        int p = atomicAdd(&g_ccnt[c], 1);
        g_trow[p] = rows[i];
        g_tcol[p] = c;
        g_tval[p] = vals[i];
    }
}

// pass 2: bucket tmp (col-grouped order) by row -> final CSR.
// which: 0 = hh, 1 = ih
__global__ void k_scatter_row(int n, int which) {
    int* rcur = (which == 0) ? g_hh_cnt : g_ih_cnt;
    int* ocol = (which == 0) ? g_hh_col : g_ih_col;
    float* oval = (which == 0) ? g_hh_val : g_ih_val;
    for (int i = blockIdx.x * blockDim.x + threadIdx.x; i < n;
         i += gridDim.x * blockDim.x) {
        int r = g_trow[i];
        int p = atomicAdd(&rcur[r], 1);
        ocol[p] = g_tcol[i];
        oval[p] = g_tval[i];
    }
}

// transpose x (B,T,I) -> g_xT (T,I,B)
__global__ void k_transpose(const float* __restrict__ x) {
    __shared__ float tile[32][Bb + 1];
    int i0 = blockIdx.x * 32;
    int t = blockIdx.y;
    int tx = threadIdx.x, ty = threadIdx.y;    // block (32, 8)
    #pragma unroll
    for (int bq = 0; bq < 8; bq++) {
        int b = ty + 8 * bq;
        tile[tx][b] = x[((size_t)b * Tt + t) * Ii + i0 + tx];
    }
    __syncthreads();
    int lin = ty * 32 + tx;                    // 0..255
    #pragma unroll
    for (int k = 0; k < 8; k++) {
        int idx = lin + 256 * k;               // 0..2047
        int iy = idx >> 6;                     // 0..31
        int b = idx & 63;
        g_xT[((size_t)t * Ii + i0 + iy) * Bb + b] = tile[iy][b];
    }
}

// ---------------- per-step kernels ----------------

__device__ __forceinline__ void spmm_accum(int s, int e, int lane,
                                           const int* __restrict__ cols,
                                           const float* __restrict__ vals,
                                           const float2* __restrict__ src,
                                           float& ax, float& ay) {
    for (int base = s; base < e; base += 32) {
        int rem = e - base;
        int c = 0; float v = 0.f;
        if (lane < rem) { c = cols[base + lane]; v = vals[base + lane]; }
        if (rem >= 32) {
            #pragma unroll
            for (int j = 0; j < 32; j++) {
                int cj = __shfl_sync(0xffffffffu, c, j);
                float vj = __shfl_sync(0xffffffffu, v, j);
                float2 hv = src[cj * (Bb / 2) + lane];
                ax = fmaf(vj, hv.x, ax);
                ay = fmaf(vj, hv.y, ay);
            }
        } else {
            for (int j = 0; j < rem; j++) {
                int cj = __shfl_sync(0xffffffffu, c, j);
                float vj = __shfl_sync(0xffffffffu, v, j);
                float2 hv = src[cj * (Bb / 2) + lane];
                ax = fmaf(vj, hv.x, ax);
                ay = fmaf(vj, hv.y, ay);
            }
        }
    }
}

// warp per output row: pre = bias + ih_spmm(x_t) + hh_spmm(h); hact = tanh(pre)
__global__ void __launch_bounds__(256) k_spmm(int t,
                                              const float* __restrict__ b_ih,
                                              const float* __restrict__ b_hh) {
    int wid = (blockIdx.x * blockDim.x + threadIdx.x) >> 5;
    int lane = threadIdx.x & 31;
    if (wid >= Hh) return;
    float bias = b_ih[wid] + b_hh[wid];
    float ax = bias, ay = bias;

    const float2* xt2 = (const float2*)(g_xT + (size_t)t * Ii * Bb);
    spmm_accum(g_ih_ptr[wid], g_ih_ptr[wid + 1], lane, g_ih_col, g_ih_val, xt2, ax, ay);

    const float2* h2 = (const float2*)g_h;
    spmm_accum(g_hh_ptr[wid], g_hh_ptr[wid + 1], lane, g_hh_col, g_hh_val, h2, ax, ay);

    float2 o;
    o.x = tanhf(ax);
    o.y = tanhf(ay);
    ((float2*)g_hact)[wid * (Bb / 2) + lane] = o;
}

// layernorm over H for one batch column + write h and out[b][t][:]
__global__ void __launch_bounds__(512) k_ln(int t,
                                            const float* __restrict__ gamma,
                                            const float* __restrict__ beta,
                                            float* __restrict__ out) {
    __shared__ float col[Hh];
    __shared__ float s1[16], s2[16];
    int b = blockIdx.x;
    int tid = threadIdx.x;
    float sum = 0.f, sq = 0.f;
    for (int r = tid; r < Hh; r += 512) {
        float v = g_hact[r * Bb + b];
        col[r] = v;
        sum += v;
        sq += v * v;
    }
    #pragma unroll
    for (int o = 16; o > 0; o >>= 1) {
        sum += __shfl_down_sync(0xffffffffu, sum, o);
        sq  += __shfl_down_sync(0xffffffffu, sq, o);
    }
    int w = tid >> 5, l = tid & 31;
    if (l == 0) { s1[w] = sum; s2[w] = sq; }
    __syncthreads();
    if (w == 0) {
        sum = (l < 16) ? s1[l] : 0.f;
        sq  = (l < 16) ? s2[l] : 0.f;
        #pragma unroll
        for (int o = 8; o > 0; o >>= 1) {
            sum += __shfl_down_sync(0xffffffffu, sum, o);
            sq  += __shfl_down_sync(0xffffffffu, sq, o);
        }
        if (l == 0) { s1[0] = sum; s2[0] = sq; }
    }
    __syncthreads();
    float mu = s1[0] * (1.0f / Hh);
    float var = s2[0] * (1.0f / Hh) - mu * mu;
    float rs = rsqrtf(var + 1e-5f);
    for (int r = tid; r < Hh; r += 512) {
        float hn = (col[r] - mu) * rs * gamma[r] + beta[r];
        g_h[r * Bb + b] = hn;
        out[((size_t)b * Tt + t) * Hh + r] = hn;
    }
}

__global__ void k_hlast(float* __restrict__ out) {
    int i = blockIdx.x * blockDim.x + threadIdx.x;   // over B*H
    if (i < Bb * Hh) {
        int b = i / Hh, r = i % Hh;
        out[(size_t)Bb * Tt * Hh + i] = g_h[r * Bb + b];
    }
}

// ---------------- launch ----------------

extern "C" void kernel_launch(void* const* d_in, const int* in_sizes, int n_in,
                              void* d_out, int out_size) {
    const float* x       = (const float*)d_in[0];
    const int*   ih_rows = (const int*)d_in[1];
    const int*   ih_cols = (const int*)d_in[2];
    const float* ih_vals = (const float*)d_in[3];
    const int*   hh_rows = (const int*)d_in[4];
    const int*   hh_cols = (const int*)d_in[5];
    const float* hh_vals = (const float*)d_in[6];
    const float* b_ih    = (const float*)d_in[7];
    const float* b_hh    = (const float*)d_in[8];
    const float* gamma   = (const float*)d_in[9];
    const float* beta    = (const float*)d_in[10];
    float* out = (float*)d_out;

    // ---- preprocessing: build CSR (cols ~ascending within row) ----
    k_zero_all<<<1024, 256>>>();

    // hh
    k_hist<<<2048, 256>>>(hh_rows, hh_cols, NNZ_HH, 0);
    k_scan<<<1, 1024>>>(0, Hh);     // col scan
    k_scan<<<1, 1024>>>(1, Hh);     // row scan
    k_scatter_col<<<2048, 256>>>(hh_rows, hh_cols, hh_vals, NNZ_HH);
    k_scatter_row<<<2048, 256>>>(NNZ_HH, 0);

    // ih (reuse tmp + col counters)
    k_zero_ccnt<<<16, 256>>>();
    k_hist<<<1024, 256>>>(ih_rows, ih_cols, NNZ_IH, 1);
    k_scan<<<1, 1024>>>(0, Ii);     // col scan (I=1024 cols)
    k_scan<<<1, 1024>>>(2, Hh);     // row scan
    k_scatter_col<<<1024, 256>>>(ih_rows, ih_cols, ih_vals, NNZ_IH);
    k_scatter_row<<<1024, 256>>>(NNZ_IH, 1);

    // x transpose (B,T,I) -> (T,I,B)
    k_transpose<<<dim3(Ii / 32, Tt), dim3(32, 8)>>>(x);

    // ---- recurrence ----
    for (int t = 0; t < Tt; t++) {
        k_spmm<<<512, 256>>>(t, b_ih, b_hh);
        k_ln<<<64, 512>>>(t, gamma, beta, out);
    }

    k_hlast<<<1024, 256>>>(out);
}

// round 2
// speedup vs baseline: 1.0624x; 1.0624x over previous
#include <cuda_runtime.h>
#include <math.h>

#define Bb 64
#define Tt 128
#define Ii 1024
#define Hh 4096
#define NNZ_IH 262144
#define NNZ_HH 1048576
#define HB (Hh * Bb)

#define NW_HH 8            // 8 col windows of 512 for hh
#define NW_IH 2            // 2 col windows of 512 for ih
#define WINC 512
#define NK_HH (NW_HH * Hh) // 32768 buckets
#define NK_IH (NW_IH * Hh) // 8192 buckets
#define NC_HH 18           // row chunks for k_hh
#define CHUNK_HH 228       // ceil(4096/18)
#define NC_IH 16
#define CHUNK_IH 256

// ---------------- device scratch ----------------
__device__ float g_xT[Tt * Ii * Bb];        // (T, I, B)  32MB
__device__ float g_ihb[Tt * Hh * Bb];       // ih partial preact per t  128MB
__device__ float g_h[HB];                   // hidden (H, B)
__device__ float g_hact[HB];                // tanh(pre)
__device__ float g_part[NW_HH * HB];        // hh window partials  8MB

__device__ int   g_hh_bptr[NK_HH + 1];
__device__ int   g_hh_bcnt[NK_HH];
__device__ int2  g_hh_pair[NNZ_HH];         // {local byte offset, val bits}

__device__ int   g_ih_bptr[NK_IH + 1];
__device__ int   g_ih_bcnt[NK_IH];
__device__ int2  g_ih_pair[NNZ_IH];         // {global byte offset in x_t, val bits}

// ---------------- prep ----------------

__global__ void k_zero_all() {
    int i = blockIdx.x * blockDim.x + threadIdx.x;    // 262144 threads
    if (i < NK_HH) g_hh_bcnt[i] = 0;
    if (i < NK_IH) g_ih_bcnt[i] = 0;
    if (i < HB) g_h[i] = 0.f;
}

__global__ void k_hist(const int* __restrict__ rows, const int* __restrict__ cols,
                       int n, int which) {
    int* cnt = (which == 0) ? g_hh_bcnt : g_ih_bcnt;
    for (int i = blockIdx.x * blockDim.x + threadIdx.x; i < n;
         i += gridDim.x * blockDim.x) {
        int key = (cols[i] >> 9) * Hh + rows[i];
        atomicAdd(&cnt[key], 1);
    }
}

// exclusive scan of cnt[0..n) -> ptr[0..n]; resets cnt to start cursors.
// single block, 1024 threads, m = n/1024 consecutive elems per thread.
__global__ void k_scan_big(int which, int n) {
    int* cnt = (which == 0) ? g_hh_bcnt : g_ih_bcnt;
    int* ptr = (which == 0) ? g_hh_bptr : g_ih_bptr;
    __shared__ int part[1024];
    int tid = threadIdx.x;
    int m = n >> 10;
    int base = tid * m;
    int sum = 0;
    for (int j = 0; j < m; j++) sum += cnt[base + j];
    part[tid] = sum;
    __syncthreads();
    for (int off = 1; off < 1024; off <<= 1) {
        int v = (tid >= off) ? part[tid - off] : 0;
        __syncthreads();
        part[tid] += v;
        __syncthreads();
    }
    int run = part[tid] - sum;
    for (int j = 0; j < m; j++) {
        int v = cnt[base + j];
        ptr[base + j] = run;
        cnt[base + j] = run;
        run += v;
    }
    if (tid == 1023) ptr[n] = part[1023];
}

// scatter into bucketed pair arrays. local=1: offset masked within window (hh)
__global__ void k_scatter(const int* __restrict__ rows, const int* __restrict__ cols,
                          const float* __restrict__ vals, int n, int which, int local) {
    int* cur = (which == 0) ? g_hh_bcnt : g_ih_bcnt;
    int2* pair = (which == 0) ? g_hh_pair : g_ih_pair;
    for (int i = blockIdx.x * blockDim.x + threadIdx.x; i < n;
         i += gridDim.x * blockDim.x) {
        int c = cols[i];
        int key = (c >> 9) * Hh + rows[i];
        int p = atomicAdd(&cur[key], 1);
        int off = (local ? (c & (WINC - 1)) : c) * (Bb * 4);
        int2 pr; pr.x = off; pr.y = __float_as_int(vals[i]);
        pair[p] = pr;
    }
}

// transpose x (B,T,I) -> g_xT (T,I,B)
__global__ void k_transpose(const float* __restrict__ x) {
    __shared__ float tile[32][Bb + 1];
    int i0 = blockIdx.x * 32;
    int t = blockIdx.y;
    int tx = threadIdx.x, ty = threadIdx.y;    // block (32, 8)
    #pragma unroll
    for (int bq = 0; bq < 8; bq++) {
        int b = ty + 8 * bq;
        tile[tx][b] = x[((size_t)b * Tt + t) * Ii + i0 + tx];
    }
    __syncthreads();
    int lin = ty * 32 + tx;
    #pragma unroll
    for (int k = 0; k < 8; k++) {
        int idx = lin + 256 * k;
        int iy = idx >> 6;
        int b = idx & 63;
        g_xT[((size_t)t * Ii + i0 + iy) * Bb + b] = tile[iy][b];
    }
}

// ---------------- ih precompute (all t) ----------------
// grid (NC_IH, Tt), 1024 threads. Windows looped inside; accums in registers.
__global__ void __launch_bounds__(1024, 1) k_ih_all() {
    int t = blockIdx.y;
    int chunk0 = blockIdx.x * CHUNK_IH;
    int lane = threadIdx.x & 31, warp = threadIdx.x >> 5;
    const char* xb = (const char*)(g_xT + (size_t)t * Ii * Bb);
    float2 acc[8];
    #pragma unroll
    for (int k = 0; k < 8; k++) { acc[k].x = 0.f; acc[k].y = 0.f; }

    for (int w = 0; w < NW_IH; w++) {
        #pragma unroll
        for (int k = 0; k < 8; k++) {
            int r = chunk0 + warp + 32 * k;
            int s = g_ih_bptr[w * Hh + r];
            int e = g_ih_bptr[w * Hh + r + 1];
            float ax = acc[k].x, ay = acc[k].y;
            #pragma unroll 4
            for (int i = s; i < e; i++) {
                int2 p = __ldg(&g_ih_pair[i]);
                float2 hv = *(const float2*)(xb + p.x + (lane << 3));
                float v = __int_as_float(p.y);
                ax = fmaf(v, hv.x, ax);
                ay = fmaf(v, hv.y, ay);
            }
            acc[k].x = ax; acc[k].y = ay;
        }
    }
    float* ob = g_ihb + (size_t)t * HB;
    #pragma unroll
    for (int k = 0; k < 8; k++) {
        int r = chunk0 + warp + 32 * k;
        ((float2*)(ob + r * Bb))[lane] = acc[k];
    }
}

// ---------------- per-step kernels ----------------

// hh windowed spmm: grid (NC_HH, NW_HH), 1024 threads, 128KB dynamic smem
__global__ void __launch_bounds__(1024, 1) k_hh() {
    extern __shared__ float sh[];                 // 512 * 64 floats
    int w = blockIdx.y;
    int chunk0 = blockIdx.x * CHUNK_HH;
    int tid = threadIdx.x;
    // stage h window (coalesced, 128KB)
    {
        const float4* src = (const float4*)(g_h + w * WINC * Bb);
        float4* dst = (float4*)sh;
        #pragma unroll
        for (int i = tid; i < WINC * Bb / 4; i += 1024) dst[i] = src[i];
    }
    __syncthreads();
    int lane = tid & 31, warp = tid >> 5;
    const char* shb = (const char*)sh;
    #pragma unroll
    for (int k = 0; k < 8; k++) {
        int local = warp + 32 * k;
        if (local >= CHUNK_HH) break;
        int r = chunk0 + local;
        if (r >= Hh) break;
        int s = g_hh_bptr[w * Hh + r];
        int e = g_hh_bptr[w * Hh + r + 1];
        float ax = 0.f, ay = 0.f;
        #pragma unroll 4
        for (int i = s; i < e; i++) {
            int2 p = __ldg(&g_hh_pair[i]);
            float2 hv = *(const float2*)(shb + p.x + (lane << 3));
            float v = __int_as_float(p.y);
            ax = fmaf(v, hv.x, ax);
            ay = fmaf(v, hv.y, ay);
        }
        float2 o; o.x = ax; o.y = ay;
        ((float2*)(g_part + (size_t)(w * Hh + r) * Bb))[lane] = o;
    }
}

// pre = biases + ihb[t] + sum_w part[w]; hact = tanh(pre)
__global__ void __launch_bounds__(1024) k_reduce(int t, const float* __restrict__ b_ih,
                                                 const float* __restrict__ b_hh) {
    int idx = blockIdx.x * blockDim.x + threadIdx.x;    // over HB
    int r = idx >> 6;
    float s = b_ih[r] + b_hh[r] + g_ihb[(size_t)t * HB + idx];
    #pragma unroll
    for (int w = 0; w < NW_HH; w++) s += g_part[(size_t)w * HB + idx];
    g_hact[idx] = tanhf(s);
}

// layernorm over H for one batch column + write h and out[b][t][:]
__global__ void __launch_bounds__(512) k_ln(int t, const float* __restrict__ gamma,
                                            const float* __restrict__ beta,
                                            float* __restrict__ out) {
    __shared__ float col[Hh];
    __shared__ float s1[16], s2[16];
    int b = blockIdx.x;
    int tid = threadIdx.x;
    float sum = 0.f, sq = 0.f;
    for (int r = tid; r < Hh; r += 512) {
        float v = g_hact[r * Bb + b];
        col[r] = v;
        sum += v;
        sq += v * v;
    }
    #pragma unroll
    for (int o = 16; o > 0; o >>= 1) {
        sum += __shfl_down_sync(0xffffffffu, sum, o);
        sq  += __shfl_down_sync(0xffffffffu, sq, o);
    }
    int w = tid >> 5, l = tid & 31;
    if (l == 0) { s1[w] = sum; s2[w] = sq; }
    __syncthreads();
    if (w == 0) {
        sum = (l < 16) ? s1[l] : 0.f;
        sq  = (l < 16) ? s2[l] : 0.f;
        #pragma unroll
        for (int o = 8; o > 0; o >>= 1) {
            sum += __shfl_down_sync(0xffffffffu, sum, o);
            sq  += __shfl_down_sync(0xffffffffu, sq, o);
        }
        if (l == 0) { s1[0] = sum; s2[0] = sq; }
    }
    __syncthreads();
    float mu = s1[0] * (1.0f / Hh);
    float var = s2[0] * (1.0f / Hh) - mu * mu;
    float rs = rsqrtf(var + 1e-5f);
    for (int r = tid; r < Hh; r += 512) {
        float hn = (col[r] - mu) * rs * gamma[r] + beta[r];
        g_h[r * Bb + b] = hn;
        out[((size_t)b * Tt + t) * Hh + r] = hn;
    }
}

__global__ void k_hlast(float* __restrict__ out) {
    int i = blockIdx.x * blockDim.x + threadIdx.x;   // over B*H
    if (i < Bb * Hh) {
        int b = i / Hh, r = i % Hh;
        out[(size_t)Bb * Tt * Hh + i] = g_h[r * Bb + b];
    }
}

// ---------------- launch ----------------

extern "C" void kernel_launch(void* const* d_in, const int* in_sizes, int n_in,
                              void* d_out, int out_size) {
    const float* x       = (const float*)d_in[0];
    const int*   ih_rows = (const int*)d_in[1];
    const int*   ih_cols = (const int*)d_in[2];
    const float* ih_vals = (const float*)d_in[3];
    const int*   hh_rows = (const int*)d_in[4];
    const int*   hh_cols = (const int*)d_in[5];
    const float* hh_vals = (const float*)d_in[6];
    const float* b_ih    = (const float*)d_in[7];
    const float* b_hh    = (const float*)d_in[8];
    const float* gamma   = (const float*)d_in[9];
    const float* beta    = (const float*)d_in[10];
    float* out = (float*)d_out;

    const int SMEM_WIN = WINC * Bb * 4;   // 131072
    cudaFuncSetAttribute(k_hh, cudaFuncAttributeMaxDynamicSharedMemorySize, SMEM_WIN);

    // ---- bucket build ----
    k_zero_all<<<1024, 256>>>();
    k_hist<<<2048, 256>>>(hh_rows, hh_cols, NNZ_HH, 0);
    k_hist<<<1024, 256>>>(ih_rows, ih_cols, NNZ_IH, 1);
    k_scan_big<<<1, 1024>>>(0, NK_HH);
    k_scan_big<<<1, 1024>>>(1, NK_IH);
    k_scatter<<<2048, 256>>>(hh_rows, hh_cols, hh_vals, NNZ_HH, 0, 1);
    k_scatter<<<1024, 256>>>(ih_rows, ih_cols, ih_vals, NNZ_IH, 1, 0);

    // ---- x transpose + ih precompute over all t ----
    k_transpose<<<dim3(Ii / 32, Tt), dim3(32, 8)>>>(x);
    k_ih_all<<<dim3(NC_IH, Tt), 1024>>>();

    // ---- recurrence ----
    for (int t = 0; t < Tt; t++) {
        k_hh<<<dim3(NC_HH, NW_HH), 1024, SMEM_WIN>>>();
        k_reduce<<<HB / 1024, 1024>>>(t, b_ih, b_hh);
        k_ln<<<64, 512>>>(t, gamma, beta, out);
    }

    k_hlast<<<1024, 256>>>(out);
}